// round 11
// baseline (speedup 1.0000x reference)
#include <cuda_runtime.h>
#include <cuda_fp16.h>
#include <cstdint>
#include <math.h>

#define NN    32
#define BSZv  512
#define NE    7
#define DIN   512
#define DHv   256
#define RHv   64
#define NPAIR 21
#define M_ROWS (NN * BSZv * NE)   // 114688
#define NCFG  128
#define NTILES 1792
#define PGRID  304

// ---------------- scratch (device globals; no allocation allowed) ------------
// packed layout (BK=64): [k64-chunk][row][64 fp16] (128B rows)
__device__ __align__(128) __half g_w0p[(size_t)(DIN / 64) * DHv * 64];
__device__ __align__(128) __half g_w1p[(size_t)(DHv / 64) * DHv * 64];
__device__ __align__(128) __half g_h1p[(size_t)(DHv / 64) * M_ROWS * 64];
__device__ float g_un[(size_t)M_ROWS * 2];
__device__ float g_pairsum[(size_t)BSZv * NCFG];

// ---------------- PTX helpers ------------------------------------------------
__device__ __forceinline__ uint32_t smem_u32(const void* p) {
    uint32_t a;
    asm("{ .reg .u64 t; cvta.to.shared.u64 t, %1; cvt.u32.u64 %0, t; }" : "=r"(a) : "l"(p));
    return a;
}
__device__ __forceinline__ void ldsm4(uint32_t a, uint32_t* r) {
    asm volatile("ldmatrix.sync.aligned.m8n8.x4.shared.b16 {%0,%1,%2,%3}, [%4];"
                 : "=r"(r[0]), "=r"(r[1]), "=r"(r[2]), "=r"(r[3]) : "r"(a));
}
__device__ __forceinline__ void mma_f16(float* c, const uint32_t* a, uint32_t b0, uint32_t b1) {
    asm volatile("mma.sync.aligned.m16n8k16.row.col.f32.f16.f16.f32 "
                 "{%0,%1,%2,%3}, {%4,%5,%6,%7}, {%8,%9}, {%0,%1,%2,%3};"
                 : "+f"(c[0]), "+f"(c[1]), "+f"(c[2]), "+f"(c[3])
                 : "r"(a[0]), "r"(a[1]), "r"(a[2]), "r"(a[3]), "r"(b0), "r"(b1));
}
#define CP16(dst, src) asm volatile("cp.async.cg.shared.global [%0], [%1], 16;" :: "r"(dst), "l"(src))
#define CPCOMMIT()     asm volatile("cp.async.commit_group;" ::: "memory")
#define CPWAIT1()      asm volatile("cp.async.wait_group 1;" ::: "memory")
#define STS128(a, v0, v1, v2, v3) \
    asm volatile("st.shared.v4.b32 [%0], {%1,%2,%3,%4};" :: "r"(a), "r"(v0), "r"(v1), "r"(v2), "r"(v3))

__device__ __forceinline__ uint32_t pack2h(__half a, __half b) {
    __half2 t = __halves2half2(a, b);
    return *reinterpret_cast<uint32_t*>(&t);
}

// ---------------- weight packing (BK64 rows) ------------------------------------
__global__ __launch_bounds__(256) void pack_weights(
    const float* __restrict__ W, __half* __restrict__ dst, int K)
{
    int idx = blockIdx.x * 256 + threadIdx.x;
    if (idx >= K * 256) return;
    int k = idx >> 8, n = idx & 255;
    size_t o = ((size_t)(k >> 6) * 256 + n) * 64 + (k & 63);
    dst[o] = __float2half_rn(W[idx]);
}

// ---------------- GEMM (fp16 mma, persistent, B-resident, BK=64) ---------------
// SMEM: [0, RES_CH*16K)  resident B chunks
//       [A_OFF, +32K)    A double buffer (2 x 16K)
//       [BS_OFF, +32K)   B stream double buffer (MODE0 only)
#define SM_BIAS 98304
#define SM_W2   99328
#define SMEM_SZ 101376

template <int KDIM, int MODE>
__global__ __launch_bounds__(256, 2) void gemm_tc(
    const float* __restrict__ Af, const __half* __restrict__ Ap,
    const __half* __restrict__ Wp, const float* __restrict__ bias,
    const float* __restrict__ W2, __half* __restrict__ outp,
    float* __restrict__ un)
{
    extern __shared__ char smem[];
    constexpr int NC = KDIM / 64;                 // GEMM1: 8, GEMM2: 4
    constexpr int RES_CH = (MODE == 0) ? 2 : 4;
    constexpr uint32_t A_OFF = RES_CH * 16384;    // 32K or 64K
    constexpr uint32_t BS_OFF = A_OFF + 32768;    // MODE0 only
    const int tid = threadIdx.x;
    const int lane = tid & 31;
    const int wid = tid >> 5;
    const int warp_m = wid >> 2, warp_n = wid & 3;
    const int bid = blockIdx.x;
    const int GRID = gridDim.x;
    const int nB = (bid & 1) * 128;

    const uint32_t sb = smem_u32(smem);
    float* biasS = (float*)(smem + SM_BIAS);
    float* W2s = (float*)(smem + SM_W2);
    biasS[tid] = bias[tid];
    if (MODE == 1) { W2s[tid] = W2[tid]; W2s[tid + 256] = W2[tid + 256]; }

    const int crow = tid >> 1;
    const int chalf = tid & 1;
    const int cxor = crow & 7;

    const uint32_t aRowOff = (uint32_t)(warp_m * 64 + (lane & 15)) * 128;
    const uint32_t aKsel = (uint32_t)(lane >> 4);
    const uint32_t bRowOff = (uint32_t)(warp_n * 32 + ((lane >> 4) << 3) + (lane & 7)) * 128;
    const uint32_t bKsel = (uint32_t)((lane >> 3) & 1);
    const uint32_t xr = (uint32_t)(lane & 7);

    const int myTiles = (NTILES - bid + GRID - 1) / GRID;
    const int total = myTiles * NC;

    float acc[4][4][4];
#pragma unroll
    for (int a = 0; a < 4; a++)
#pragma unroll
        for (int b = 0; b < 4; b++)
#pragma unroll
            for (int q = 0; q < 4; q++) acc[a][b][q] = 0.f;

    float rA[32];   // MODE0 staging: full 64-k thread slice (2 halves)

    // ---- resident B chunks, one-time ----
    {
#pragma unroll
        for (int p = 0; p < RES_CH; p++) {
            const char* src = (const char*)(Wp + ((size_t)p * 256 + nB + crow) * 64 + chalf * 32);
            uint32_t dst = sb + p * 16384 + crow * 128;
#pragma unroll
            for (int j = 0; j < 2; j++)
                CP16(dst + ((uint32_t)(2 * chalf + j) ^ cxor) * 16, src + j * 16);
            const char* src2 = src + 64;   // other 64B half of the row? no —
            // row is 128B; thread covers halves [32*chalf, 32*chalf+32) = 64B = 4 groups
            // groups 4*chalf + j for j in 0..3:
            (void)src2;
        }
        // redo properly: 4 CP16 per chunk per thread
    }
    // NOTE: the loop above issued only 2 of 4; issue remaining 2 per chunk:
    {
#pragma unroll
        for (int p = 0; p < RES_CH; p++) {
            const char* src = (const char*)(Wp + ((size_t)p * 256 + nB + crow) * 64 + chalf * 32);
            uint32_t dst = sb + p * 16384 + crow * 128;
#pragma unroll
            for (int j = 2; j < 4; j++)
                CP16(dst + ((uint32_t)(2 * chalf + j) ^ cxor) * 16, src + (j - 2) * 16 + 32);
        }
        CPCOMMIT();
    }
    // Correction note: groups must be 4*chalf + j with src + j*16, j=0..3.
    // The two blocks above together write groups {2c,2c+1,2c+2,2c+3} from
    // src bytes {0,16,32,48}: with c=chalf this equals groups 2*chalf..2*chalf+3.
    // For chalf=1 that is groups 2..5, overlapping chalf=0 groups 0..3 at 2,3!
    // -> fixed below by a clean re-copy pass for safety.
    __syncthreads();
    {
#pragma unroll
        for (int p = 0; p < RES_CH; p++) {
            const __half* src = Wp + ((size_t)p * 256 + nB + crow) * 64 + chalf * 32;
            char* dstb = smem + p * 16384 + crow * 128;
#pragma unroll
            for (int j = 0; j < 4; j++) {
                uint4 v = *(const uint4*)((const char*)src + j * 16);
                *(uint4*)(dstb + (((uint32_t)(4 * chalf + j)) ^ cxor) * 16) = v;
            }
        }
    }
    __syncthreads();

    auto loadA_regs = [&](int s) {            // MODE0: 32 floats (full 64-k slice/thread? no: half-row)
        int i = s / NC, c = s % NC;
        int t = bid + i * GRID;
        size_t mB = (size_t)(t >> 1) * 128;
        const float* p = Af + (mB + crow) * KDIM + c * 64 + chalf * 32;
#pragma unroll
        for (int q = 0; q < 8; q++)
            *(float4*)(rA + 4 * q) = *(const float4*)(p + 4 * q);
    };
    auto storeA_regs = [&](int buf) {
        uint32_t dst = sb + A_OFF + (uint32_t)buf * 16384 + crow * 128;
        uint32_t hh[16];
#pragma unroll
        for (int q = 0; q < 16; q++)
            hh[q] = pack2h(__float2half_rn(rA[2 * q]), __float2half_rn(rA[2 * q + 1]));
#pragma unroll
        for (int g = 0; g < 4; g++)
            STS128(dst + ((uint32_t)(4 * chalf + g) ^ cxor) * 16,
                   hh[4 * g], hh[4 * g + 1], hh[4 * g + 2], hh[4 * g + 3]);
    };
    auto prefetch = [&](int ss) {
        if (ss < total) {
            int c = ss % NC;
            int buf = ss & 1;
            if (MODE == 1) {
                int i = ss / NC;
                int t = bid + i * GRID;
                size_t mB = (size_t)(t >> 1) * 128;
                const char* srcA = (const char*)(Ap + ((size_t)c * M_ROWS + mB + crow) * 64 + chalf * 32);
                uint32_t dstA = sb + A_OFF + (uint32_t)buf * 16384 + crow * 128;
#pragma unroll
                for (int j = 0; j < 4; j++)
                    CP16(dstA + ((uint32_t)(4 * chalf + j) ^ cxor) * 16, srcA + j * 16);
            } else if (c >= RES_CH) {
                const char* srcB = (const char*)(Wp + ((size_t)c * 256 + nB + crow) * 64 + chalf * 32);
                uint32_t dstB = sb + BS_OFF + (uint32_t)buf * 16384 + crow * 128;
#pragma unroll
                for (int j = 0; j < 4; j++)
                    CP16(dstB + ((uint32_t)(4 * chalf + j) ^ cxor) * 16, srcB + j * 16);
            }
        }
        CPCOMMIT();
    };
    auto compute = [&](int sidx) {
        int c = sidx % NC;
        uint32_t Ab = sb + A_OFF + (uint32_t)(sidx & 1) * 16384 + aRowOff;
        uint32_t Bb;
        if (MODE == 0 && c >= RES_CH) Bb = sb + BS_OFF + (uint32_t)(sidx & 1) * 16384 + bRowOff;
        else Bb = sb + (uint32_t)c * 16384 + bRowOff;
#pragma unroll
        for (int ks = 0; ks < 4; ks++) {
            uint32_t bh[8];
            ldsm4(Bb + (((uint32_t)(2 * ks) + bKsel) ^ xr) * 16, bh);
            ldsm4(Bb + 2048 + (((uint32_t)(2 * ks) + bKsel) ^ xr) * 16, bh + 4);
#pragma unroll
            for (int mi = 0; mi < 4; mi++) {
                uint32_t ah[4];
                ldsm4(Ab + mi * 2048 + (((uint32_t)(2 * ks) + aKsel) ^ xr) * 16, ah);
#pragma unroll
                for (int nj = 0; nj < 4; nj++)
                    mma_f16(acc[mi][nj], ah, bh[2 * nj], bh[2 * nj + 1]);
            }
        }
    };

    const int rloc = warp_m * 64 + (lane >> 2);
    const int nl0 = warp_n * 32 + (lane & 3) * 2;

    // ---- prologue ----
    prefetch(0);
    if (MODE == 0) {
        loadA_regs(0); storeA_regs(0);
        if (total > 1) { loadA_regs(1); storeA_regs(1); }
    }

    // ---- main loop ----
    for (int s = 0; s < total; s++) {
        prefetch(s + 1);
        CPWAIT1();
        __syncthreads();
        compute(s);

        if ((s % NC) == NC - 1) {
            const int t = bid + (s / NC) * GRID;
            const size_t mBase = (size_t)(t >> 1) * 128;
            if (MODE == 0) {
#pragma unroll
                for (int mi = 0; mi < 4; mi++)
#pragma unroll
                    for (int nj = 0; nj < 4; nj++) {
                        int nl = nl0 + nj * 8;
                        float b0v = biasS[nB + nl], b1v = biasS[nB + nl + 1];
                        float v00 = fmaxf(acc[mi][nj][0] + b0v, 0.f);
                        float v01 = fmaxf(acc[mi][nj][1] + b1v, 0.f);
                        float v10 = fmaxf(acc[mi][nj][2] + b0v, 0.f);
                        float v11 = fmaxf(acc[mi][nj][3] + b1v, 0.f);
                        int gn = nB + nl;
                        int cpk = gn >> 6, slot = gn & 63;
                        size_t r0 = mBase + rloc + mi * 16;
                        size_t o0 = ((size_t)cpk * M_ROWS + r0) * 64 + slot;
                        size_t o1 = o0 + 8 * 64;
                        *(uint32_t*)(outp + o0) =
                            pack2h(__float2half_rn(v00), __float2half_rn(v01));
                        *(uint32_t*)(outp + o1) =
                            pack2h(__float2half_rn(v10), __float2half_rn(v11));
                        acc[mi][nj][0] = 0.f; acc[mi][nj][1] = 0.f;
                        acc[mi][nj][2] = 0.f; acc[mi][nj][3] = 0.f;
                    }
            } else {
                float up[16];
#pragma unroll
                for (int i = 0; i < 16; i++) up[i] = 0.f;
#pragma unroll
                for (int mi = 0; mi < 4; mi++)
#pragma unroll
                    for (int nj = 0; nj < 4; nj++) {
                        int nl = nl0 + nj * 8;
                        float b0v = biasS[nB + nl], b1v = biasS[nB + nl + 1];
                        float w00 = W2s[2 * (nB + nl)],     w01 = W2s[2 * (nB + nl) + 1];
                        float w10 = W2s[2 * (nB + nl) + 2], w11 = W2s[2 * (nB + nl) + 3];
                        float v00 = fmaxf(acc[mi][nj][0] + b0v, 0.f);
                        float v01 = fmaxf(acc[mi][nj][1] + b1v, 0.f);
                        float v10 = fmaxf(acc[mi][nj][2] + b0v, 0.f);
                        float v11 = fmaxf(acc[mi][nj][3] + b1v, 0.f);
                        up[mi * 4 + 0] += v00 * w00 + v01 * w10;
                        up[mi * 4 + 1] += v00 * w01 + v01 * w11;
                        up[mi * 4 + 2] += v10 * w00 + v11 * w10;
                        up[mi * 4 + 3] += v10 * w01 + v11 * w11;
                        acc[mi][nj][0] = 0.f; acc[mi][nj][1] = 0.f;
                        acc[mi][nj][2] = 0.f; acc[mi][nj][3] = 0.f;
                    }
#pragma unroll
                for (int k = 1; k <= 2; k <<= 1)
#pragma unroll
                    for (int i = 0; i < 16; i++)
                        up[i] += __shfl_xor_sync(0xffffffffu, up[i], k);
                if ((lane & 3) == 0) {
#pragma unroll
                    for (int mi = 0; mi < 4; mi++) {
                        size_t r0 = mBase + rloc + mi * 16;
                        size_t r1 = r0 + 8;
                        atomicAdd(&un[r0 * 2 + 0], up[mi * 4 + 0]);
                        atomicAdd(&un[r0 * 2 + 1], up[mi * 4 + 1]);
                        atomicAdd(&un[r1 * 2 + 0], up[mi * 4 + 2]);
                        atomicAdd(&un[r1 * 2 + 1], up[mi * 4 + 3]);
                    }
                }
            }
        }

        __syncthreads();   // WAR guard for buffer reuse

        if (MODE == 0) {
            if (s + 2 < total) {
                loadA_regs(s + 2);
                storeA_regs((s + 2) & 1);
            }
        }
    }
}

// -------- binary MLP + pairwise config sums ----------------------------------
__global__ __launch_bounds__(128) void binary_kernel(
    const float* __restrict__ ctx, const float* __restrict__ R0,
    const float* __restrict__ r0, const float* __restrict__ R1,
    const float* __restrict__ r1, float* __restrict__ pairsum)
{
    __shared__ float cd[NPAIR][5];
    __shared__ float R0s[5][RHv];
    __shared__ float r0s[RHv];
    __shared__ float R1s[RHv][3];
    __shared__ float r1s[3];
    __shared__ float h2s[NPAIR][RHv];
    __shared__ float bp4s[NPAIR][4];

    int b = blockIdx.x, t = threadIdx.x;
    for (int i = t; i < NPAIR * 5; i += 128) cd[i / 5][i % 5] = ctx[b * NPAIR * 5 + i];
    for (int i = t; i < 5 * RHv; i += 128) R0s[i / RHv][i % RHv] = R0[i];
    if (t < RHv) r0s[t] = r0[t];
    for (int i = t; i < RHv * 3; i += 128) R1s[i / 3][i % 3] = R1[i];
    if (t < 3) r1s[t] = r1[t];
    __syncthreads();

    for (int idx = t; idx < NPAIR * RHv; idx += 128) {
        int p = idx / RHv, u = idx % RHv;
        float v = r0s[u];
#pragma unroll
        for (int x = 0; x < 5; x++) v += cd[p][x] * R0s[x][u];
        h2s[p][u] = fmaxf(v, 0.f);
    }
    __syncthreads();

    if (t < NPAIR * 3) {
        int p = t / 3, y = t % 3;
        float v = r1s[y];
#pragma unroll
        for (int u = 0; u < RHv; u++) v += h2s[p][u] * R1s[u][y];
        if (y == 0) bp4s[p][0] = v;
        else if (y == 1) { bp4s[p][1] = v; bp4s[p][2] = v; }
        else bp4s[p][3] = v;
    }
    __syncthreads();

    int s = t;
    float accv = 0.f;
    int p = 0;
#pragma unroll
    for (int i = 0; i < NE; i++)
#pragma unroll
        for (int j = i + 1; j < NE; j++) {
            int bi = (s >> (6 - i)) & 1;
            int bj = (s >> (6 - j)) & 1;
            accv += bp4s[p][bi * 2 + bj];
            p++;
        }
    pairsum[(size_t)b * NCFG + s] = accv;
}

// ---------------- joint + lse + marginals: one warp per (n,b) -----------------
__global__ __launch_bounds__(256) void joint_kernel(
    const float* __restrict__ un, const float* __restrict__ ps,
    const float* __restrict__ b2v, float* __restrict__ out_marg,
    float* __restrict__ out_joint)
{
    int w = blockIdx.x * 8 + (threadIdx.x >> 5);
    int lane = threadIdx.x & 31;
    int b = w & (BSZv - 1), n = w >> 9;
    size_t nb = (size_t)n * BSZv + b;

    float val = 0.f;
    if (lane < 14) val = un[nb * 14 + lane] + b2v[lane & 1];
    float u[14];
#pragma unroll
    for (int i = 0; i < 14; i++) u[i] = __shfl_sync(0xffffffffu, val, i);

    float j[4], e[4];
    float mx = -1e30f;
#pragma unroll
    for (int q = 0; q < 4; q++) {
        int s = q * 32 + lane;
        float t = ps[(size_t)b * NCFG + s];
#pragma unroll
        for (int i = 0; i < NE; i++) t += u[i * 2 + ((s >> (6 - i)) & 1)];
        j[q] = t;
        mx = fmaxf(mx, t);
    }
#pragma unroll
    for (int o = 16; o; o >>= 1) mx = fmaxf(mx, __shfl_xor_sync(0xffffffffu, mx, o));

    float p1[NE], p0[NE];
#pragma unroll
    for (int i = 0; i < NE; i++) { p1[i] = 0.f; p0[i] = 0.f; }
#pragma unroll
    for (int q = 0; q < 4; q++) {
        int s = q * 32 + lane;
        e[q] = __expf(j[q] - mx);
#pragma unroll
        for (int i = 0; i < NE; i++) {
            if ((s >> (6 - i)) & 1) p1[i] += e[q];
            else p0[i] += e[q];
        }
    }
#pragma unroll
    for (int o = 16; o; o >>= 1)
#pragma unroll
        for (int i = 0; i < NE; i++) {
            p1[i] += __shfl_xor_sync(0xffffffffu, p1[i], o);
            p0[i] += __shfl_xor_sync(0xffffffffu, p0[i], o);
        }

    float lt = __logf(p1[0] + p0[0]);
#pragma unroll
    for (int q = 0; q < 4; q++)
        out_joint[nb * NCFG + q * 32 + lane] = j[q] - mx - lt;
    if (lane < NE)
        out_marg[nb * NE + lane] = __logf(p1[lane]) - __logf(p0[lane]);
}

// ---------------- launch -------------------------------------------------------
extern "C" void kernel_launch(void* const* d_in, const int* in_sizes, int n_in,
                              void* d_out, int out_size)
{
    const float* input = (const float*)d_in[0];
    const float* ctx   = (const float*)d_in[1];
    const float* W0 = (const float*)d_in[4];
    const float* b0 = (const float*)d_in[5];
    const float* W1 = (const float*)d_in[6];
    const float* b1 = (const float*)d_in[7];
    const float* W2 = (const float*)d_in[8];
    const float* b2 = (const float*)d_in[9];
    const float* R0 = (const float*)d_in[10];
    const float* r0 = (const float*)d_in[11];
    const float* R1 = (const float*)d_in[12];
    const float* r1 = (const float*)d_in[13];

    float* out = (float*)d_out;
    float* out_marg = out;
    float* out_joint = out + (size_t)M_ROWS;

    __half *w0p, *w1p, *h1p;
    float *un, *psum;
    cudaGetSymbolAddress((void**)&w0p, g_w0p);
    cudaGetSymbolAddress((void**)&w1p, g_w1p);
    cudaGetSymbolAddress((void**)&h1p, g_h1p);
    cudaGetSymbolAddress((void**)&un, g_un);
    cudaGetSymbolAddress((void**)&psum, g_pairsum);

    cudaFuncSetAttribute(gemm_tc<DIN, 0>, cudaFuncAttributeMaxDynamicSharedMemorySize, SMEM_SZ);
    cudaFuncSetAttribute(gemm_tc<DHv, 1>, cudaFuncAttributeMaxDynamicSharedMemorySize, SMEM_SZ);

    pack_weights<<<DIN, 256>>>(W0, w0p, DIN);
    pack_weights<<<DHv, 256>>>(W1, w1p, DHv);
    cudaMemsetAsync(un, 0, (size_t)M_ROWS * 2 * sizeof(float));

    gemm_tc<DIN, 0><<<PGRID, 256, SMEM_SZ>>>(
        input, nullptr, w0p, b0, nullptr, h1p, nullptr);
    gemm_tc<DHv, 1><<<PGRID, 256, SMEM_SZ>>>(
        nullptr, h1p, w1p, b1, W2, nullptr, un);
    binary_kernel<<<BSZv, 128>>>(ctx, R0, r0, R1, r1, psum);
    joint_kernel<<<(NN * BSZv) / 8, 256>>>(un, psum, b2, out_marg, out_joint);
}

// round 12
// speedup vs baseline: 1.7137x; 1.7137x over previous
#include <cuda_runtime.h>
#include <cuda_fp16.h>
#include <cstdint>
#include <math.h>

#define NN    32
#define BSZv  512
#define NE    7
#define DIN   512
#define DHv   256
#define RHv   64
#define NPAIR 21
#define M_ROWS (NN * BSZv * NE)   // 114688
#define NCFG  128
#define NTILES 1792
#define PGRID  304

// ---------------- scratch (device globals; no allocation allowed) ------------
// packed (BK=32): [k32-chunk][row][32 fp16] (64B rows)
__device__ __align__(128) __half g_w0p[(size_t)(DIN / 32) * DHv * 32];
__device__ __align__(128) __half g_w1p[(size_t)(DHv / 32) * DHv * 32];
__device__ __align__(128) __half g_h1p[(size_t)(DHv / 32) * M_ROWS * 32];
__device__ float g_un[(size_t)M_ROWS * 2];
__device__ float g_pairsum[(size_t)BSZv * NCFG];

// ---------------- PTX helpers ------------------------------------------------
__device__ __forceinline__ uint32_t smem_u32(const void* p) {
    uint32_t a;
    asm("{ .reg .u64 t; cvta.to.shared.u64 t, %1; cvt.u32.u64 %0, t; }" : "=r"(a) : "l"(p));
    return a;
}
__device__ __forceinline__ void ldsm4(uint32_t a, uint32_t* r) {
    asm volatile("ldmatrix.sync.aligned.m8n8.x4.shared.b16 {%0,%1,%2,%3}, [%4];"
                 : "=r"(r[0]), "=r"(r[1]), "=r"(r[2]), "=r"(r[3]) : "r"(a));
}
__device__ __forceinline__ void mma_f16(float* c, const uint32_t* a, uint32_t b0, uint32_t b1) {
    asm volatile("mma.sync.aligned.m16n8k16.row.col.f32.f16.f16.f32 "
                 "{%0,%1,%2,%3}, {%4,%5,%6,%7}, {%8,%9}, {%0,%1,%2,%3};"
                 : "+f"(c[0]), "+f"(c[1]), "+f"(c[2]), "+f"(c[3])
                 : "r"(a[0]), "r"(a[1]), "r"(a[2]), "r"(a[3]), "r"(b0), "r"(b1));
}
#define CP16(dst, src) asm volatile("cp.async.cg.shared.global [%0], [%1], 16;" :: "r"(dst), "l"(src))
#define CPCOMMIT()     asm volatile("cp.async.commit_group;" ::: "memory")
#define CPWAIT2()      asm volatile("cp.async.wait_group 2;" ::: "memory")
#define STS128(a, v0, v1, v2, v3) \
    asm volatile("st.shared.v4.b32 [%0], {%1,%2,%3,%4};" :: "r"(a), "r"(v0), "r"(v1), "r"(v2), "r"(v3))

__device__ __forceinline__ uint32_t pack2h(__half a, __half b) {
    __half2 t = __halves2half2(a, b);
    return *reinterpret_cast<uint32_t*>(&t);
}

// ---------------- weight packing (BK32 rows) ------------------------------------
__global__ __launch_bounds__(256) void pack_weights(
    const float* __restrict__ W, __half* __restrict__ dst, int K)
{
    int idx = blockIdx.x * 256 + threadIdx.x;
    if (idx >= K * 256) return;
    int k = idx >> 8, n = idx & 255;
    size_t o = ((size_t)(k >> 5) * 256 + n) * 32 + (k & 31);
    dst[o] = __float2half_rn(W[idx]);
}

// ---------------- GEMM (fp16 mma, persistent, B-resident, 1 barrier/iter) ------
// SMEM: [0, RES) resident B pair-regions (MODE0: 32K = chunks 0-3; MODE1: 64K = 0-7)
//       [A_OFF, +32K)  A 4-slot ring (slot q: region q>>1, group-parity q&1)
//       [BS_OFF, +32K) B stream 4-slot ring (MODE0 chunks >= 4)
#define SM_BIAS 98304
#define SM_W2   99328
#define SMEM_SZ 101376

template <int KDIM, int MODE>
__global__ __launch_bounds__(256, 2) void gemm_tc(
    const float* __restrict__ Af, const __half* __restrict__ Ap,
    const __half* __restrict__ Wp, const float* __restrict__ bias,
    const float* __restrict__ W2, __half* __restrict__ outp,
    float* __restrict__ un)
{
    extern __shared__ char smem[];
    constexpr int NC = KDIM / 32;                   // 16 or 8
    constexpr int RES_CH = (MODE == 0) ? 4 : 8;     // resident chunks
    constexpr uint32_t A_OFF = (MODE == 0) ? 32768u : 65536u;
    constexpr uint32_t BS_OFF = A_OFF + 32768u;     // MODE0 only
    const int tid = threadIdx.x;
    const int lane = tid & 31;
    const int wid = tid >> 5;
    const int warp_m = wid >> 2, warp_n = wid & 3;
    const int bid = blockIdx.x;
    const int GRID = gridDim.x;
    const int nB = (bid & 1) * 128;

    const uint32_t sb = smem_u32(smem);
    float* biasS = (float*)(smem + SM_BIAS);
    float* W2s = (float*)(smem + SM_W2);
    biasS[tid] = bias[tid];
    if (MODE == 1) { W2s[tid] = W2[tid]; W2s[tid + 256] = W2[tid + 256]; }

    const int crow = tid >> 1;
    const int chalf = tid & 1;
    const int cxor = crow & 7;

    const uint32_t aRowOff = (uint32_t)(warp_m * 64 + (lane & 15)) * 128;
    const uint32_t aKsel = (uint32_t)(lane >> 4);
    const uint32_t bRowOff = (uint32_t)(warp_n * 32 + ((lane >> 4) << 3) + (lane & 7)) * 128;
    const uint32_t bKsel = (uint32_t)((lane >> 3) & 1);
    const uint32_t xr = (uint32_t)(lane & 7);

    const int myTiles = (NTILES - bid + GRID - 1) / GRID;
    const int total = myTiles * NC;

    float acc[4][4][4];
#pragma unroll
    for (int a = 0; a < 4; a++)
#pragma unroll
        for (int b = 0; b < 4; b++)
#pragma unroll
            for (int q = 0; q < 4; q++) acc[a][b][q] = 0.f;

    float rA[16];   // MODE0 staging

    // ---- resident B: pair-region p holds chunk 2p (groups 0-3) & 2p+1 (4-7) ----
    {
#pragma unroll
        for (int p = 0; p < RES_CH / 2; p++) {
            int c = 2 * p + chalf;
            const char* src = (const char*)(Wp + ((size_t)c * 256 + nB + crow) * 32);
            uint32_t dst = sb + (uint32_t)p * 16384 + crow * 128;
#pragma unroll
            for (int j = 0; j < 4; j++)
                CP16(dst + ((uint32_t)(4 * chalf + j) ^ cxor) * 16, src + j * 16);
        }
        CPCOMMIT();
    }

    auto loadA_regs = [&](int s) {            // MODE0 only
        int i = s / NC, c = s % NC;
        int t = bid + i * GRID;
        size_t mB = (size_t)(t >> 1) * 128;
        const float* p = Af + (mB + crow) * KDIM + c * 32 + chalf * 16;
        *(float4*)(rA)      = *(const float4*)(p);
        *(float4*)(rA + 4)  = *(const float4*)(p + 4);
        *(float4*)(rA + 8)  = *(const float4*)(p + 8);
        *(float4*)(rA + 12) = *(const float4*)(p + 12);
    };
    auto storeA_regs = [&](uint32_t q) {      // slot q = chunk_index & 3
        uint32_t dst = sb + A_OFF + (q >> 1) * 16384 + crow * 128;
        uint32_t gb = 4u * (q & 1);
        uint32_t hh[8];
#pragma unroll
        for (int k = 0; k < 8; k++)
            hh[k] = pack2h(__float2half_rn(rA[2 * k]), __float2half_rn(rA[2 * k + 1]));
        STS128(dst + ((gb + 2 * chalf + 0) ^ cxor) * 16, hh[0], hh[1], hh[2], hh[3]);
        STS128(dst + ((gb + 2 * chalf + 1) ^ cxor) * 16, hh[4], hh[5], hh[6], hh[7]);
    };
    auto prefetch = [&](int ss) {
        if (ss < total) {
            int c = ss % NC;
            uint32_t q = (uint32_t)ss & 3;
            uint32_t gb = 4u * (q & 1);
            if (MODE == 1) {
                int i = ss / NC;
                int t = bid + i * GRID;
                size_t mB = (size_t)(t >> 1) * 128;
                const char* srcA = (const char*)(Ap + ((size_t)c * M_ROWS + mB + crow) * 32 + chalf * 16);
                uint32_t dstA = sb + A_OFF + (q >> 1) * 16384 + crow * 128;
#pragma unroll
                for (int j = 0; j < 2; j++)
                    CP16(dstA + ((gb + 2 * chalf + j) ^ cxor) * 16, srcA + j * 16);
            } else if (c >= RES_CH) {
                const char* srcB = (const char*)(Wp + ((size_t)c * 256 + nB + crow) * 32 + chalf * 16);
                uint32_t dstB = sb + BS_OFF + (q >> 1) * 16384 + crow * 128;
#pragma unroll
                for (int j = 0; j < 2; j++)
                    CP16(dstB + ((gb + 2 * chalf + j) ^ cxor) * 16, srcB + j * 16);
            }
        }
        CPCOMMIT();
    };
    auto compute = [&](int sidx) {
        int c = sidx % NC;
        uint32_t q = (uint32_t)sidx & 3;
        uint32_t ga = 4u * (q & 1);
        uint32_t Ab = sb + A_OFF + (q >> 1) * 16384 + aRowOff;
        uint32_t Bb, gb;
        if (MODE == 0 && c >= RES_CH) {
            Bb = sb + BS_OFF + (q >> 1) * 16384 + bRowOff;
            gb = ga;
        } else {
            Bb = sb + (uint32_t)(c >> 1) * 16384 + bRowOff;
            gb = 4u * (uint32_t)(c & 1);
        }
#pragma unroll
        for (int ks = 0; ks < 2; ks++) {
            uint32_t bh[8];
            ldsm4(Bb + ((gb + 2 * ks + bKsel) ^ xr) * 16, bh);
            ldsm4(Bb + 2048 + ((gb + 2 * ks + bKsel) ^ xr) * 16, bh + 4);
#pragma unroll
            for (int mi = 0; mi < 4; mi++) {
                uint32_t ah[4];
                ldsm4(Ab + mi * 2048 + ((ga + 2 * ks + aKsel) ^ xr) * 16, ah);
#pragma unroll
                for (int nj = 0; nj < 4; nj++)
                    mma_f16(acc[mi][nj], ah, bh[2 * nj], bh[2 * nj + 1]);
            }
        }
    };

    const int rloc = warp_m * 64 + (lane >> 2);
    const int nl0 = warp_n * 32 + (lane & 3) * 2;

    // ---- prologue: streams 0,1 prefetched; MODE0 slots 0,1 staged, chunk2 in rA
    prefetch(0);
    prefetch(1);
    if (MODE == 0) {
        loadA_regs(0); storeA_regs(0);
        if (total > 1) { loadA_regs(1); storeA_regs(1); }
        if (total > 2) loadA_regs(2);
    }

    // ---- main loop: ONE barrier per iteration ----
    for (int s = 0; s < total; s++) {
        prefetch(s + 2);
        CPWAIT2();
        __syncthreads();
        compute(s);

        if ((s % NC) == NC - 1) {
            const int t = bid + (s / NC) * GRID;
            const size_t mBase = (size_t)(t >> 1) * 128;
            if (MODE == 0) {
#pragma unroll
                for (int mi = 0; mi < 4; mi++)
#pragma unroll
                    for (int nj = 0; nj < 4; nj++) {
                        int nl = nl0 + nj * 8;
                        float b0v = biasS[nB + nl], b1v = biasS[nB + nl + 1];
                        float v00 = fmaxf(acc[mi][nj][0] + b0v, 0.f);
                        float v01 = fmaxf(acc[mi][nj][1] + b1v, 0.f);
                        float v10 = fmaxf(acc[mi][nj][2] + b0v, 0.f);
                        float v11 = fmaxf(acc[mi][nj][3] + b1v, 0.f);
                        int gn = nB + nl;
                        int cpk = gn >> 5, slot = gn & 31;
                        size_t r0 = mBase + rloc + mi * 16;
                        size_t o0 = ((size_t)cpk * M_ROWS + r0) * 32 + slot;
                        size_t o1 = o0 + 8 * 32;
                        *(uint32_t*)(outp + o0) =
                            pack2h(__float2half_rn(v00), __float2half_rn(v01));
                        *(uint32_t*)(outp + o1) =
                            pack2h(__float2half_rn(v10), __float2half_rn(v11));
                        acc[mi][nj][0] = 0.f; acc[mi][nj][1] = 0.f;
                        acc[mi][nj][2] = 0.f; acc[mi][nj][3] = 0.f;
                    }
            } else {
                float up[16];
#pragma unroll
                for (int i = 0; i < 16; i++) up[i] = 0.f;
#pragma unroll
                for (int mi = 0; mi < 4; mi++)
#pragma unroll
                    for (int nj = 0; nj < 4; nj++) {
                        int nl = nl0 + nj * 8;
                        float b0v = biasS[nB + nl], b1v = biasS[nB + nl + 1];
                        float w00 = W2s[2 * (nB + nl)],     w01 = W2s[2 * (nB + nl) + 1];
                        float w10 = W2s[2 * (nB + nl) + 2], w11 = W2s[2 * (nB + nl) + 3];
                        float v00 = fmaxf(acc[mi][nj][0] + b0v, 0.f);
                        float v01 = fmaxf(acc[mi][nj][1] + b1v, 0.f);
                        float v10 = fmaxf(acc[mi][nj][2] + b0v, 0.f);
                        float v11 = fmaxf(acc[mi][nj][3] + b1v, 0.f);
                        up[mi * 4 + 0] += v00 * w00 + v01 * w10;
                        up[mi * 4 + 1] += v00 * w01 + v01 * w11;
                        up[mi * 4 + 2] += v10 * w00 + v11 * w10;
                        up[mi * 4 + 3] += v10 * w01 + v11 * w11;
                        acc[mi][nj][0] = 0.f; acc[mi][nj][1] = 0.f;
                        acc[mi][nj][2] = 0.f; acc[mi][nj][3] = 0.f;
                    }
#pragma unroll
                for (int k = 1; k <= 2; k <<= 1)
#pragma unroll
                    for (int i = 0; i < 16; i++)
                        up[i] += __shfl_xor_sync(0xffffffffu, up[i], k);
                if ((lane & 3) == 0) {
#pragma unroll
                    for (int mi = 0; mi < 4; mi++) {
                        size_t r0 = mBase + rloc + mi * 16;
                        size_t r1 = r0 + 8;
                        atomicAdd(&un[r0 * 2 + 0], up[mi * 4 + 0]);
                        atomicAdd(&un[r0 * 2 + 1], up[mi * 4 + 1]);
                        atomicAdd(&un[r1 * 2 + 0], up[mi * 4 + 2]);
                        atomicAdd(&un[r1 * 2 + 1], up[mi * 4 + 3]);
                    }
                }
            }
        }

        if (MODE == 0) {
            if (s + 2 < total) {
                storeA_regs((uint32_t)(s + 2) & 3);   // safe: slot last read at s-2
                if (s + 3 < total) loadA_regs(s + 3);
            }
        }
    }
}

// -------- binary MLP + pairwise config sums ----------------------------------
__global__ __launch_bounds__(128) void binary_kernel(
    const float* __restrict__ ctx, const float* __restrict__ R0,
    const float* __restrict__ r0, const float* __restrict__ R1,
    const float* __restrict__ r1, float* __restrict__ pairsum)
{
    __shared__ float cd[NPAIR][5];
    __shared__ float R0s[5][RHv];
    __shared__ float r0s[RHv];
    __shared__ float R1s[RHv][3];
    __shared__ float r1s[3];
    __shared__ float h2s[NPAIR][RHv];
    __shared__ float bp4s[NPAIR][4];

    int b = blockIdx.x, t = threadIdx.x;
    for (int i = t; i < NPAIR * 5; i += 128) cd[i / 5][i % 5] = ctx[b * NPAIR * 5 + i];
    for (int i = t; i < 5 * RHv; i += 128) R0s[i / RHv][i % RHv] = R0[i];
    if (t < RHv) r0s[t] = r0[t];
    for (int i = t; i < RHv * 3; i += 128) R1s[i / 3][i % 3] = R1[i];
    if (t < 3) r1s[t] = r1[t];
    __syncthreads();

    for (int idx = t; idx < NPAIR * RHv; idx += 128) {
        int p = idx / RHv, u = idx % RHv;
        float v = r0s[u];
#pragma unroll
        for (int x = 0; x < 5; x++) v += cd[p][x] * R0s[x][u];
        h2s[p][u] = fmaxf(v, 0.f);
    }
    __syncthreads();

    if (t < NPAIR * 3) {
        int p = t / 3, y = t % 3;
        float v = r1s[y];
#pragma unroll
        for (int u = 0; u < RHv; u++) v += h2s[p][u] * R1s[u][y];
        if (y == 0) bp4s[p][0] = v;
        else if (y == 1) { bp4s[p][1] = v; bp4s[p][2] = v; }
        else bp4s[p][3] = v;
    }
    __syncthreads();

    int s = t;
    float accv = 0.f;
    int p = 0;
#pragma unroll
    for (int i = 0; i < NE; i++)
#pragma unroll
        for (int j = i + 1; j < NE; j++) {
            int bi = (s >> (6 - i)) & 1;
            int bj = (s >> (6 - j)) & 1;
            accv += bp4s[p][bi * 2 + bj];
            p++;
        }
    pairsum[(size_t)b * NCFG + s] = accv;
}

// ---------------- joint + lse + marginals: one warp per (n,b) -----------------
__global__ __launch_bounds__(256) void joint_kernel(
    const float* __restrict__ un, const float* __restrict__ ps,
    const float* __restrict__ b2v, float* __restrict__ out_marg,
    float* __restrict__ out_joint)
{
    int w = blockIdx.x * 8 + (threadIdx.x >> 5);
    int lane = threadIdx.x & 31;
    int b = w & (BSZv - 1), n = w >> 9;
    size_t nb = (size_t)n * BSZv + b;

    float val = 0.f;
    if (lane < 14) val = un[nb * 14 + lane] + b2v[lane & 1];
    float u[14];
#pragma unroll
    for (int i = 0; i < 14; i++) u[i] = __shfl_sync(0xffffffffu, val, i);

    float j[4], e[4];
    float mx = -1e30f;
#pragma unroll
    for (int q = 0; q < 4; q++) {
        int s = q * 32 + lane;
        float t = ps[(size_t)b * NCFG + s];
#pragma unroll
        for (int i = 0; i < NE; i++) t += u[i * 2 + ((s >> (6 - i)) & 1)];
        j[q] = t;
        mx = fmaxf(mx, t);
    }
#pragma unroll
    for (int o = 16; o; o >>= 1) mx = fmaxf(mx, __shfl_xor_sync(0xffffffffu, mx, o));

    float p1[NE], p0[NE];
#pragma unroll
    for (int i = 0; i < NE; i++) { p1[i] = 0.f; p0[i] = 0.f; }
#pragma unroll
    for (int q = 0; q < 4; q++) {
        int s = q * 32 + lane;
        e[q] = __expf(j[q] - mx);
#pragma unroll
        for (int i = 0; i < NE; i++) {
            if ((s >> (6 - i)) & 1) p1[i] += e[q];
            else p0[i] += e[q];
        }
    }
#pragma unroll
    for (int o = 16; o; o >>= 1)
#pragma unroll
        for (int i = 0; i < NE; i++) {
            p1[i] += __shfl_xor_sync(0xffffffffu, p1[i], o);
            p0[i] += __shfl_xor_sync(0xffffffffu, p0[i], o);
        }

    float lt = __logf(p1[0] + p0[0]);
#pragma unroll
    for (int q = 0; q < 4; q++)
        out_joint[nb * NCFG + q * 32 + lane] = j[q] - mx - lt;
    if (lane < NE)
        out_marg[nb * NE + lane] = __logf(p1[lane]) - __logf(p0[lane]);
}

// ---------------- launch -------------------------------------------------------
extern "C" void kernel_launch(void* const* d_in, const int* in_sizes, int n_in,
                              void* d_out, int out_size)
{
    const float* input = (const float*)d_in[0];
    const float* ctx   = (const float*)d_in[1];
    const float* W0 = (const float*)d_in[4];
    const float* b0 = (const float*)d_in[5];
    const float* W1 = (const float*)d_in[6];
    const float* b1 = (const float*)d_in[7];
    const float* W2 = (const float*)d_in[8];
    const float* b2 = (const float*)d_in[9];
    const float* R0 = (const float*)d_in[10];
    const float* r0 = (const float*)d_in[11];
    const float* R1 = (const float*)d_in[12];
    const float* r1 = (const float*)d_in[13];

    float* out = (float*)d_out;
    float* out_marg = out;
    float* out_joint = out + (size_t)M_ROWS;

    __half *w0p, *w1p, *h1p;
    float *un, *psum;
    cudaGetSymbolAddress((void**)&w0p, g_w0p);
    cudaGetSymbolAddress((void**)&w1p, g_w1p);
    cudaGetSymbolAddress((void**)&h1p, g_h1p);
    cudaGetSymbolAddress((void**)&un, g_un);
    cudaGetSymbolAddress((void**)&psum, g_pairsum);

    cudaFuncSetAttribute(gemm_tc<DIN, 0>, cudaFuncAttributeMaxDynamicSharedMemorySize, SMEM_SZ);
    cudaFuncSetAttribute(gemm_tc<DHv, 1>, cudaFuncAttributeMaxDynamicSharedMemorySize, SMEM_SZ);

    pack_weights<<<DIN, 256>>>(W0, w0p, DIN);
    pack_weights<<<DHv, 256>>>(W1, w1p, DHv);
    cudaMemsetAsync(un, 0, (size_t)M_ROWS * 2 * sizeof(float));

    gemm_tc<DIN, 0><<<PGRID, 256, SMEM_SZ>>>(
        input, nullptr, w0p, b0, nullptr, h1p, nullptr);
    gemm_tc<DHv, 1><<<PGRID, 256, SMEM_SZ>>>(
        nullptr, h1p, w1p, b1, W2, nullptr, un);
    binary_kernel<<<BSZv, 128>>>(ctx, R0, r0, R1, r1, psum);
    joint_kernel<<<(NN * BSZv) / 8, 256>>>(un, psum, b2, out_marg, out_joint);
}

// round 13
// speedup vs baseline: 1.7262x; 1.0073x over previous
#include <cuda_runtime.h>
#include <cuda_fp16.h>
#include <cstdint>
#include <math.h>

#define NN    32
#define BSZv  512
#define NE    7
#define DIN   512
#define DHv   256
#define RHv   64
#define NPAIR 21
#define M_ROWS (NN * BSZv * NE)   // 114688
#define NCFG  128
#define NTILES 1792
#define PGRID  304

// ---------------- scratch (device globals; no allocation allowed) ------------
__device__ __align__(128) __half g_w0p[(size_t)(DIN / 32) * DHv * 32];
__device__ __align__(128) __half g_w1p[(size_t)(DHv / 32) * DHv * 32];
__device__ __align__(128) __half g_h1p[(size_t)(DHv / 32) * M_ROWS * 32];
__device__ float g_un[(size_t)M_ROWS * 2];
__device__ float g_pairsum[(size_t)BSZv * NCFG];

// ---------------- PTX helpers ------------------------------------------------
__device__ __forceinline__ uint32_t smem_u32(const void* p) {
    uint32_t a;
    asm("{ .reg .u64 t; cvta.to.shared.u64 t, %1; cvt.u32.u64 %0, t; }" : "=r"(a) : "l"(p));
    return a;
}
__device__ __forceinline__ void ldsm4(uint32_t a, uint32_t* r) {
    asm volatile("ldmatrix.sync.aligned.m8n8.x4.shared.b16 {%0,%1,%2,%3}, [%4];"
                 : "=r"(r[0]), "=r"(r[1]), "=r"(r[2]), "=r"(r[3]) : "r"(a));
}
__device__ __forceinline__ void mma_f16(float* c, const uint32_t* a, uint32_t b0, uint32_t b1) {
    asm volatile("mma.sync.aligned.m16n8k16.row.col.f32.f16.f16.f32 "
                 "{%0,%1,%2,%3}, {%4,%5,%6,%7}, {%8,%9}, {%0,%1,%2,%3};"
                 : "+f"(c[0]), "+f"(c[1]), "+f"(c[2]), "+f"(c[3])
                 : "r"(a[0]), "r"(a[1]), "r"(a[2]), "r"(a[3]), "r"(b0), "r"(b1));
}
#define CP16(dst, src) asm volatile("cp.async.cg.shared.global [%0], [%1], 16;" :: "r"(dst), "l"(src))
#define CPCOMMIT()     asm volatile("cp.async.commit_group;" ::: "memory")
#define CPWAIT2()      asm volatile("cp.async.wait_group 2;" ::: "memory")
#define STS128(a, v0, v1, v2, v3) \
    asm volatile("st.shared.v4.b32 [%0], {%1,%2,%3,%4};" :: "r"(a), "r"(v0), "r"(v1), "r"(v2), "r"(v3))

// pack two fp32 -> fp16x2 in ONE instruction (lo = first arg)
__device__ __forceinline__ uint32_t packf2(float lo, float hi) {
    uint32_t d;
    asm("cvt.rn.f16x2.f32 %0, %1, %2;" : "=r"(d) : "f"(hi), "f"(lo));
    return d;
}

// ---------------- weight packing (BK32 rows) ------------------------------------
__global__ __launch_bounds__(256) void pack_weights(
    const float* __restrict__ W, __half* __restrict__ dst, int K)
{
    int idx = blockIdx.x * 256 + threadIdx.x;
    if (idx >= K * 256) return;
    int k = idx >> 8, n = idx & 255;
    size_t o = ((size_t)(k >> 5) * 256 + n) * 32 + (k & 31);
    dst[o] = __float2half_rn(W[idx]);
}

// ---------------- GEMM (fp16 mma, persistent, B-resident, 1 barrier/iter) ------
#define SM_BIAS 98304
#define SM_W2   99328
#define SMEM_SZ 101376

template <int KDIM, int MODE>
__global__ __launch_bounds__(256, 2) void gemm_tc(
    const float* __restrict__ Af, const __half* __restrict__ Ap,
    const __half* __restrict__ Wp, const float* __restrict__ bias,
    const float* __restrict__ W2, __half* __restrict__ outp,
    float* __restrict__ un)
{
    extern __shared__ char smem[];
    constexpr int NC = KDIM / 32;                   // 16 or 8
    constexpr int RES_CH = (MODE == 0) ? 4 : 8;
    constexpr uint32_t A_OFF = (MODE == 0) ? 32768u : 65536u;
    constexpr uint32_t BS_OFF = A_OFF + 32768u;
    const int tid = threadIdx.x;
    const int lane = tid & 31;
    const int wid = tid >> 5;
    const int warp_m = wid >> 2, warp_n = wid & 3;
    const int bid = blockIdx.x;
    const int GRID = gridDim.x;
    const int nB = (bid & 1) * 128;

    const uint32_t sb = smem_u32(smem);
    float* biasS = (float*)(smem + SM_BIAS);
    float* W2s = (float*)(smem + SM_W2);
    biasS[tid] = bias[tid];
    if (MODE == 1) { W2s[tid] = W2[tid]; W2s[tid + 256] = W2[tid + 256]; }

    const int crow = tid >> 1;
    const int chalf = tid & 1;
    const int cxor = crow & 7;

    const uint32_t aRowOff = (uint32_t)(warp_m * 64 + (lane & 15)) * 128;
    const uint32_t aKsel = (uint32_t)(lane >> 4);
    const uint32_t bRowOff = (uint32_t)(warp_n * 32 + ((lane >> 4) << 3) + (lane & 7)) * 128;
    const uint32_t bKsel = (uint32_t)((lane >> 3) & 1);
    const uint32_t xr = (uint32_t)(lane & 7);

    const int myTiles = (NTILES - bid + GRID - 1) / GRID;
    const int total = myTiles * NC;

    float acc[4][4][4];
#pragma unroll
    for (int a = 0; a < 4; a++)
#pragma unroll
        for (int b = 0; b < 4; b++)
#pragma unroll
            for (int q = 0; q < 4; q++) acc[a][b][q] = 0.f;

    float rA[16];   // MODE0 staging

    // ---- resident B ----
    {
#pragma unroll
        for (int p = 0; p < RES_CH / 2; p++) {
            int c = 2 * p + chalf;
            const char* src = (const char*)(Wp + ((size_t)c * 256 + nB + crow) * 32);
            uint32_t dst = sb + (uint32_t)p * 16384 + crow * 128;
#pragma unroll
            for (int j = 0; j < 4; j++)
                CP16(dst + ((uint32_t)(4 * chalf + j) ^ cxor) * 16, src + j * 16);
        }
        CPCOMMIT();
    }

    auto loadA_regs = [&](int s) {            // MODE0 only
        int i = s / NC, c = s % NC;
        int t = bid + i * GRID;
        size_t mB = (size_t)(t >> 1) * 128;
        const float* p = Af + (mB + crow) * KDIM + c * 32 + chalf * 16;
        *(float4*)(rA)      = *(const float4*)(p);
        *(float4*)(rA + 4)  = *(const float4*)(p + 4);
        *(float4*)(rA + 8)  = *(const float4*)(p + 8);
        *(float4*)(rA + 12) = *(const float4*)(p + 12);
    };
    auto storeA_regs = [&](uint32_t q) {
        uint32_t dst = sb + A_OFF + (q >> 1) * 16384 + crow * 128;
        uint32_t gb = 4u * (q & 1);
        uint32_t hh[8];
#pragma unroll
        for (int k = 0; k < 8; k++)
            hh[k] = packf2(rA[2 * k], rA[2 * k + 1]);
        STS128(dst + ((gb + 2 * chalf + 0) ^ cxor) * 16, hh[0], hh[1], hh[2], hh[3]);
        STS128(dst + ((gb + 2 * chalf + 1) ^ cxor) * 16, hh[4], hh[5], hh[6], hh[7]);
    };
    auto prefetch = [&](int ss) {
        if (ss < total) {
            int c = ss % NC;
            uint32_t q = (uint32_t)ss & 3;
            uint32_t gb = 4u * (q & 1);
            if (MODE == 1) {
                int i = ss / NC;
                int t = bid + i * GRID;
                size_t mB = (size_t)(t >> 1) * 128;
                const char* srcA = (const char*)(Ap + ((size_t)c * M_ROWS + mB + crow) * 32 + chalf * 16);
                uint32_t dstA = sb + A_OFF + (q >> 1) * 16384 + crow * 128;
#pragma unroll
                for (int j = 0; j < 2; j++)
                    CP16(dstA + ((gb + 2 * chalf + j) ^ cxor) * 16, srcA + j * 16);
            } else if (c >= RES_CH) {
                const char* srcB = (const char*)(Wp + ((size_t)c * 256 + nB + crow) * 32 + chalf * 16);
                uint32_t dstB = sb + BS_OFF + (q >> 1) * 16384 + crow * 128;
#pragma unroll
                for (int j = 0; j < 2; j++)
                    CP16(dstB + ((gb + 2 * chalf + j) ^ cxor) * 16, srcB + j * 16);
            }
        }
        CPCOMMIT();
    };
    auto compute = [&](int sidx) {
        int c = sidx % NC;
        uint32_t q = (uint32_t)sidx & 3;
        uint32_t ga = 4u * (q & 1);
        uint32_t Ab = sb + A_OFF + (q >> 1) * 16384 + aRowOff;
        uint32_t Bb, gb;
        if (MODE == 0 && c >= RES_CH) {
            Bb = sb + BS_OFF + (q >> 1) * 16384 + bRowOff;
            gb = ga;
        } else {
            Bb = sb + (uint32_t)(c >> 1) * 16384 + bRowOff;
            gb = 4u * (uint32_t)(c & 1);
        }
        if (MODE == 1) {
            // full fragment pipeline: load all 24 frag regs, then 32 MMAs
            uint32_t bF[2][8], aF[2][16];
#pragma unroll
            for (int ks = 0; ks < 2; ks++) {
                ldsm4(Bb + ((gb + 2 * ks + bKsel) ^ xr) * 16, bF[ks]);
                ldsm4(Bb + 2048 + ((gb + 2 * ks + bKsel) ^ xr) * 16, bF[ks] + 4);
#pragma unroll
                for (int mi = 0; mi < 4; mi++)
                    ldsm4(Ab + mi * 2048 + ((ga + 2 * ks + aKsel) ^ xr) * 16, aF[ks] + 4 * mi);
            }
#pragma unroll
            for (int ks = 0; ks < 2; ks++)
#pragma unroll
                for (int mi = 0; mi < 4; mi++)
#pragma unroll
                    for (int nj = 0; nj < 4; nj++)
                        mma_f16(acc[mi][nj], aF[ks] + 4 * mi, bF[ks][2 * nj], bF[ks][2 * nj + 1]);
        } else {
            // light pipeline: B fragments double-buffered (rA stays live)
            uint32_t bF[2][8];
            ldsm4(Bb + ((gb + bKsel) ^ xr) * 16, bF[0]);
            ldsm4(Bb + 2048 + ((gb + bKsel) ^ xr) * 16, bF[0] + 4);
#pragma unroll
            for (int ks = 0; ks < 2; ks++) {
                if (ks == 0) {
                    ldsm4(Bb + ((gb + 2 + bKsel) ^ xr) * 16, bF[1]);
                    ldsm4(Bb + 2048 + ((gb + 2 + bKsel) ^ xr) * 16, bF[1] + 4);
                }
#pragma unroll
                for (int mi = 0; mi < 4; mi++) {
                    uint32_t ah[4];
                    ldsm4(Ab + mi * 2048 + ((ga + 2 * ks + aKsel) ^ xr) * 16, ah);
#pragma unroll
                    for (int nj = 0; nj < 4; nj++)
                        mma_f16(acc[mi][nj], ah, bF[ks][2 * nj], bF[ks][2 * nj + 1]);
                }
            }
        }
    };

    const int rloc = warp_m * 64 + (lane >> 2);
    const int nl0 = warp_n * 32 + (lane & 3) * 2;

    // ---- prologue ----
    prefetch(0);
    prefetch(1);
    if (MODE == 0) {
        loadA_regs(0); storeA_regs(0);
        if (total > 1) { loadA_regs(1); storeA_regs(1); }
        if (total > 2) loadA_regs(2);
    }

    // ---- main loop: ONE barrier per iteration ----
    for (int s = 0; s < total; s++) {
        prefetch(s + 2);
        CPWAIT2();
        __syncthreads();
        compute(s);

        if ((s % NC) == NC - 1) {
            const int t = bid + (s / NC) * GRID;
            const size_t mBase = (size_t)(t >> 1) * 128;
            if (MODE == 0) {
#pragma unroll
                for (int mi = 0; mi < 4; mi++)
#pragma unroll
                    for (int nj = 0; nj < 4; nj++) {
                        int nl = nl0 + nj * 8;
                        float b0v = biasS[nB + nl], b1v = biasS[nB + nl + 1];
                        float v00 = fmaxf(acc[mi][nj][0] + b0v, 0.f);
                        float v01 = fmaxf(acc[mi][nj][1] + b1v, 0.f);
                        float v10 = fmaxf(acc[mi][nj][2] + b0v, 0.f);
                        float v11 = fmaxf(acc[mi][nj][3] + b1v, 0.f);
                        int gn = nB + nl;
                        int cpk = gn >> 5, slot = gn & 31;
                        size_t r0 = mBase + rloc + mi * 16;
                        size_t o0 = ((size_t)cpk * M_ROWS + r0) * 32 + slot;
                        size_t o1 = o0 + 8 * 32;
                        *(uint32_t*)(outp + o0) = packf2(v00, v01);
                        *(uint32_t*)(outp + o1) = packf2(v10, v11);
                        acc[mi][nj][0] = 0.f; acc[mi][nj][1] = 0.f;
                        acc[mi][nj][2] = 0.f; acc[mi][nj][3] = 0.f;
                    }
            } else {
                float up[16];
#pragma unroll
                for (int i = 0; i < 16; i++) up[i] = 0.f;
#pragma unroll
                for (int mi = 0; mi < 4; mi++)
#pragma unroll
                    for (int nj = 0; nj < 4; nj++) {
                        int nl = nl0 + nj * 8;
                        float b0v = biasS[nB + nl], b1v = biasS[nB + nl + 1];
                        float w00 = W2s[2 * (nB + nl)],     w01 = W2s[2 * (nB + nl) + 1];
                        float w10 = W2s[2 * (nB + nl) + 2], w11 = W2s[2 * (nB + nl) + 3];
                        float v00 = fmaxf(acc[mi][nj][0] + b0v, 0.f);
                        float v01 = fmaxf(acc[mi][nj][1] + b1v, 0.f);
                        float v10 = fmaxf(acc[mi][nj][2] + b0v, 0.f);
                        float v11 = fmaxf(acc[mi][nj][3] + b1v, 0.f);
                        up[mi * 4 + 0] += v00 * w00 + v01 * w10;
                        up[mi * 4 + 1] += v00 * w01 + v01 * w11;
                        up[mi * 4 + 2] += v10 * w00 + v11 * w10;
                        up[mi * 4 + 3] += v10 * w01 + v11 * w11;
                        acc[mi][nj][0] = 0.f; acc[mi][nj][1] = 0.f;
                        acc[mi][nj][2] = 0.f; acc[mi][nj][3] = 0.f;
                    }
#pragma unroll
                for (int k = 1; k <= 2; k <<= 1)
#pragma unroll
                    for (int i = 0; i < 16; i++)
                        up[i] += __shfl_xor_sync(0xffffffffu, up[i], k);
                if ((lane & 3) == 0) {
#pragma unroll
                    for (int mi = 0; mi < 4; mi++) {
                        size_t r0 = mBase + rloc + mi * 16;
                        size_t r1 = r0 + 8;
                        atomicAdd(&un[r0 * 2 + 0], up[mi * 4 + 0]);
                        atomicAdd(&un[r0 * 2 + 1], up[mi * 4 + 1]);
                        atomicAdd(&un[r1 * 2 + 0], up[mi * 4 + 2]);
                        atomicAdd(&un[r1 * 2 + 1], up[mi * 4 + 3]);
                    }
                }
            }
        }

        if (MODE == 0) {
            if (s + 2 < total) {
                storeA_regs((uint32_t)(s + 2) & 3);
                if (s + 3 < total) loadA_regs(s + 3);
            }
        }
    }
}

// -------- binary MLP + pairwise config sums ----------------------------------
__global__ __launch_bounds__(128) void binary_kernel(
    const float* __restrict__ ctx, const float* __restrict__ R0,
    const float* __restrict__ r0, const float* __restrict__ R1,
    const float* __restrict__ r1, float* __restrict__ pairsum)
{
    __shared__ float cd[NPAIR][5];
    __shared__ float R0s[5][RHv];
    __shared__ float r0s[RHv];
    __shared__ float R1s[RHv][3];
    __shared__ float r1s[3];
    __shared__ float h2s[NPAIR][RHv];
    __shared__ float bp4s[NPAIR][4];

    int b = blockIdx.x, t = threadIdx.x;
    for (int i = t; i < NPAIR * 5; i += 128) cd[i / 5][i % 5] = ctx[b * NPAIR * 5 + i];
    for (int i = t; i < 5 * RHv; i += 128) R0s[i / RHv][i % RHv] = R0[i];
    if (t < RHv) r0s[t] = r0[t];
    for (int i = t; i < RHv * 3; i += 128) R1s[i / 3][i % 3] = R1[i];
    if (t < 3) r1s[t] = r1[t];
    __syncthreads();

    for (int idx = t; idx < NPAIR * RHv; idx += 128) {
        int p = idx / RHv, u = idx % RHv;
        float v = r0s[u];
#pragma unroll
        for (int x = 0; x < 5; x++) v += cd[p][x] * R0s[x][u];
        h2s[p][u] = fmaxf(v, 0.f);
    }
    __syncthreads();

    if (t < NPAIR * 3) {
        int p = t / 3, y = t % 3;
        float v = r1s[y];
#pragma unroll
        for (int u = 0; u < RHv; u++) v += h2s[p][u] * R1s[u][y];
        if (y == 0) bp4s[p][0] = v;
        else if (y == 1) { bp4s[p][1] = v; bp4s[p][2] = v; }
        else bp4s[p][3] = v;
    }
    __syncthreads();

    int s = t;
    float accv = 0.f;
    int p = 0;
#pragma unroll
    for (int i = 0; i < NE; i++)
#pragma unroll
        for (int j = i + 1; j < NE; j++) {
            int bi = (s >> (6 - i)) & 1;
            int bj = (s >> (6 - j)) & 1;
            accv += bp4s[p][bi * 2 + bj];
            p++;
        }
    pairsum[(size_t)b * NCFG + s] = accv;
}

// ---------------- joint + lse + marginals: one warp per (n,b) -----------------
__global__ __launch_bounds__(256) void joint_kernel(
    const float* __restrict__ un, const float* __restrict__ ps,
    const float* __restrict__ b2v, float* __restrict__ out_marg,
    float* __restrict__ out_joint)
{
    int w = blockIdx.x * 8 + (threadIdx.x >> 5);
    int lane = threadIdx.x & 31;
    int b = w & (BSZv - 1), n = w >> 9;
    size_t nb = (size_t)n * BSZv + b;

    float val = 0.f;
    if (lane < 14) val = un[nb * 14 + lane] + b2v[lane & 1];
    float u[14];
#pragma unroll
    for (int i = 0; i < 14; i++) u[i] = __shfl_sync(0xffffffffu, val, i);

    float j[4], e[4];
    float mx = -1e30f;
#pragma unroll
    for (int q = 0; q < 4; q++) {
        int s = q * 32 + lane;
        float t = ps[(size_t)b * NCFG + s];
#pragma unroll
        for (int i = 0; i < NE; i++) t += u[i * 2 + ((s >> (6 - i)) & 1)];
        j[q] = t;
        mx = fmaxf(mx, t);
    }
#pragma unroll
    for (int o = 16; o; o >>= 1) mx = fmaxf(mx, __shfl_xor_sync(0xffffffffu, mx, o));

    float p1[NE], p0[NE];
#pragma unroll
    for (int i = 0; i < NE; i++) { p1[i] = 0.f; p0[i] = 0.f; }
#pragma unroll
    for (int q = 0; q < 4; q++) {
        int s = q * 32 + lane;
        e[q] = __expf(j[q] - mx);
#pragma unroll
        for (int i = 0; i < NE; i++) {
            if ((s >> (6 - i)) & 1) p1[i] += e[q];
            else p0[i] += e[q];
        }
    }
#pragma unroll
    for (int o = 16; o; o >>= 1)
#pragma unroll
        for (int i = 0; i < NE; i++) {
            p1[i] += __shfl_xor_sync(0xffffffffu, p1[i], o);
            p0[i] += __shfl_xor_sync(0xffffffffu, p0[i], o);
        }

    float lt = __logf(p1[0] + p0[0]);
#pragma unroll
    for (int q = 0; q < 4; q++)
        out_joint[nb * NCFG + q * 32 + lane] = j[q] - mx - lt;
    if (lane < NE)
        out_marg[nb * NE + lane] = __logf(p1[lane]) - __logf(p0[lane]);
}

// ---------------- launch -------------------------------------------------------
extern "C" void kernel_launch(void* const* d_in, const int* in_sizes, int n_in,
                              void* d_out, int out_size)
{
    const float* input = (const float*)d_in[0];
    const float* ctx   = (const float*)d_in[1];
    const float* W0 = (const float*)d_in[4];
    const float* b0 = (const float*)d_in[5];
    const float* W1 = (const float*)d_in[6];
    const float* b1 = (const float*)d_in[7];
    const float* W2 = (const float*)d_in[8];
    const float* b2 = (const float*)d_in[9];
    const float* R0 = (const float*)d_in[10];
    const float* r0 = (const float*)d_in[11];
    const float* R1 = (const float*)d_in[12];
    const float* r1 = (const float*)d_in[13];

    float* out = (float*)d_out;
    float* out_marg = out;
    float* out_joint = out + (size_t)M_ROWS;

    __half *w0p, *w1p, *h1p;
    float *un, *psum;
    cudaGetSymbolAddress((void**)&w0p, g_w0p);
    cudaGetSymbolAddress((void**)&w1p, g_w1p);
    cudaGetSymbolAddress((void**)&h1p, g_h1p);
    cudaGetSymbolAddress((void**)&un, g_un);
    cudaGetSymbolAddress((void**)&psum, g_pairsum);

    cudaFuncSetAttribute(gemm_tc<DIN, 0>, cudaFuncAttributeMaxDynamicSharedMemorySize, SMEM_SZ);
    cudaFuncSetAttribute(gemm_tc<DHv, 1>, cudaFuncAttributeMaxDynamicSharedMemorySize, SMEM_SZ);

    pack_weights<<<DIN, 256>>>(W0, w0p, DIN);
    pack_weights<<<DHv, 256>>>(W1, w1p, DHv);
    cudaMemsetAsync(un, 0, (size_t)M_ROWS * 2 * sizeof(float));

    gemm_tc<DIN, 0><<<PGRID, 256, SMEM_SZ>>>(
        input, nullptr, w0p, b0, nullptr, h1p, nullptr);
    gemm_tc<DHv, 1><<<PGRID, 256, SMEM_SZ>>>(
        nullptr, h1p, w1p, b1, W2, nullptr, un);
    binary_kernel<<<BSZv, 128>>>(ctx, R0, r0, R1, r1, psum);
    joint_kernel<<<(NN * BSZv) / 8, 256>>>(un, psum, b2, out_marg, out_joint);
}

// round 14
// speedup vs baseline: 1.8114x; 1.0494x over previous
#include <cuda_runtime.h>
#include <cuda_fp16.h>
#include <cstdint>
#include <math.h>

#define NN    32
#define BSZv  512
#define NE    7
#define DIN   512
#define DHv   256
#define RHv   64
#define NPAIR 21
#define M_ROWS (NN * BSZv * NE)   // 114688
#define NCFG  128
#define NTILES 896                // m-tiles only; CTA covers full N=256
#define PGRID  152

// ---------------- scratch (device globals; no allocation allowed) ------------
__device__ __align__(128) __half g_w0p[(size_t)(DIN / 32) * DHv * 32];
__device__ __align__(128) __half g_w1p[(size_t)(DHv / 32) * DHv * 32];
__device__ __align__(128) __half g_h1p[(size_t)(DHv / 32) * M_ROWS * 32];
__device__ float g_un[(size_t)M_ROWS * 2];
__device__ float g_pairsum[(size_t)BSZv * NCFG];

// ---------------- PTX helpers ------------------------------------------------
__device__ __forceinline__ uint32_t smem_u32(const void* p) {
    uint32_t a;
    asm("{ .reg .u64 t; cvta.to.shared.u64 t, %1; cvt.u32.u64 %0, t; }" : "=r"(a) : "l"(p));
    return a;
}
__device__ __forceinline__ void ldsm4(uint32_t a, uint32_t* r) {
    asm volatile("ldmatrix.sync.aligned.m8n8.x4.shared.b16 {%0,%1,%2,%3}, [%4];"
                 : "=r"(r[0]), "=r"(r[1]), "=r"(r[2]), "=r"(r[3]) : "r"(a));
}
__device__ __forceinline__ void mma_f16(float* c, const uint32_t* a, uint32_t b0, uint32_t b1) {
    asm volatile("mma.sync.aligned.m16n8k16.row.col.f32.f16.f16.f32 "
                 "{%0,%1,%2,%3}, {%4,%5,%6,%7}, {%8,%9}, {%0,%1,%2,%3};"
                 : "+f"(c[0]), "+f"(c[1]), "+f"(c[2]), "+f"(c[3])
                 : "r"(a[0]), "r"(a[1]), "r"(a[2]), "r"(a[3]), "r"(b0), "r"(b1));
}
#define CP16(dst, src) asm volatile("cp.async.cg.shared.global [%0], [%1], 16;" :: "r"(dst), "l"(src))
#define CPCOMMIT()     asm volatile("cp.async.commit_group;" ::: "memory")
#define CPWAIT2()      asm volatile("cp.async.wait_group 2;" ::: "memory")
#define STS128(a, v0, v1, v2, v3) \
    asm volatile("st.shared.v4.b32 [%0], {%1,%2,%3,%4};" :: "r"(a), "r"(v0), "r"(v1), "r"(v2), "r"(v3))

__device__ __forceinline__ uint32_t packf2(float lo, float hi) {
    uint32_t d;
    asm("cvt.rn.f16x2.f32 %0, %1, %2;" : "=r"(d) : "f"(hi), "f"(lo));
    return d;
}

// ---------------- weight packing (BK32 rows) ------------------------------------
__global__ __launch_bounds__(256) void pack_weights(
    const float* __restrict__ W, __half* __restrict__ dst, int K)
{
    int idx = blockIdx.x * 256 + threadIdx.x;
    if (idx >= K * 256) return;
    int k = idx >> 8, n = idx & 255;
    size_t o = ((size_t)(k >> 5) * 256 + n) * 32 + (k & 31);
    dst[o] = __float2half_rn(W[idx]);
}

// ---------------- GEMM: 128x256 CTA tile, 64x64 warp tile, 1 CTA/SM ------------
// B pair-region: 32KB = 256 rows x 128B; chunk 2p -> groups 0-3, 2p+1 -> groups 4-7
// Resident: 4 pair-regions (8 chunks, 128KB). MODE0 streams chunks 8-15.
// A ring: 32KB at A_OFF, 2 x (128 rows x 128B) regions, slot q -> region q>>1, parity q&1
#define RES_SZ   131072u
#define A_OFF    131072u
#define BS_OFF   163840u           // MODE0 only: 2 x 32KB stream regions
// MODE0: bias @ 229376 (1KB)  -> total 230400
// MODE1: bias @ 163840 (1KB), W2 @ 164864 (2KB) -> total 166912
#define SMEM_SZ0 230400
#define SMEM_SZ1 166912

template <int KDIM, int MODE>
__global__ __launch_bounds__(256, 1) void gemm_tc(
    const float* __restrict__ Af, const __half* __restrict__ Ap,
    const __half* __restrict__ Wp, const float* __restrict__ bias,
    const float* __restrict__ W2, __half* __restrict__ outp,
    float* __restrict__ un)
{
    extern __shared__ char smem[];
    constexpr int NC = KDIM / 32;                   // 16 or 8
    constexpr int RES_CH = 8;                       // resident chunks (both modes)
    constexpr uint32_t SM_BIAS = (MODE == 0) ? 229376u : 163840u;
    constexpr uint32_t SM_W2v  = 164864u;           // MODE1 only
    const int tid = threadIdx.x;
    const int lane = tid & 31;
    const int wid = tid >> 5;
    const int warp_m = wid >> 2, warp_n = wid & 3;  // warp tile 64(M) x 64(N)
    const int bid = blockIdx.x;
    const int GRID = gridDim.x;

    const uint32_t sb = smem_u32(smem);
    float* biasS = (float*)(smem + SM_BIAS);
    float* W2s = (float*)(smem + SM_W2v);
    biasS[tid] = bias[tid];
    if (MODE == 1) { W2s[tid] = W2[tid]; W2s[tid + 256] = W2[tid + 256]; }

    const int crow = tid >> 1;           // 0..127 (A staging)
    const int chalf = tid & 1;
    const int cxor = crow & 7;

    const uint32_t aRowOff = (uint32_t)(warp_m * 64 + (lane & 15)) * 128;
    const uint32_t aKsel = (uint32_t)(lane >> 4);
    const uint32_t bRowOff = (uint32_t)(warp_n * 64 + ((lane >> 4) << 3) + (lane & 7)) * 128;
    const uint32_t bKsel = (uint32_t)((lane >> 3) & 1);
    const uint32_t xr = (uint32_t)(lane & 7);

    const int myTiles = (NTILES - bid + GRID - 1) / GRID;
    const int total = myTiles * NC;

    float acc[4][8][4];
#pragma unroll
    for (int a = 0; a < 4; a++)
#pragma unroll
        for (int b = 0; b < 8; b++)
#pragma unroll
            for (int q = 0; q < 4; q++) acc[a][b][q] = 0.f;

    float rA[16];   // MODE0 staging

    // ---- resident B: 4 pair-regions x 256 rows; thread = one row, 8 CP16/region
    {
        const int row = tid;             // 0..255
        const uint32_t rx = (uint32_t)(row & 7);
#pragma unroll
        for (int p = 0; p < RES_CH / 2; p++) {
#pragma unroll
            for (int e = 0; e < 2; e++) {
                const char* src = (const char*)(Wp + ((size_t)(2 * p + e) * 256 + row) * 32);
                uint32_t dst = sb + (uint32_t)p * 32768 + (uint32_t)row * 128;
#pragma unroll
                for (int j = 0; j < 4; j++)
                    CP16(dst + (((uint32_t)(4 * e + j)) ^ rx) * 16, src + j * 16);
            }
        }
        CPCOMMIT();
    }

    auto loadA_regs = [&](int s) {            // MODE0 only
        int i = s / NC, c = s % NC;
        int t = bid + i * GRID;
        size_t mB = (size_t)t * 128;
        const float* p = Af + (mB + crow) * KDIM + c * 32 + chalf * 16;
        *(float4*)(rA)      = *(const float4*)(p);
        *(float4*)(rA + 4)  = *(const float4*)(p + 4);
        *(float4*)(rA + 8)  = *(const float4*)(p + 8);
        *(float4*)(rA + 12) = *(const float4*)(p + 12);
    };
    auto storeA_regs = [&](uint32_t q) {
        uint32_t dst = sb + A_OFF + (q >> 1) * 16384 + crow * 128;
        uint32_t gb = 4u * (q & 1);
        uint32_t hh[8];
#pragma unroll
        for (int k = 0; k < 8; k++)
            hh[k] = packf2(rA[2 * k], rA[2 * k + 1]);
        STS128(dst + ((gb + 2 * chalf + 0) ^ cxor) * 16, hh[0], hh[1], hh[2], hh[3]);
        STS128(dst + ((gb + 2 * chalf + 1) ^ cxor) * 16, hh[4], hh[5], hh[6], hh[7]);
    };
    auto prefetch = [&](int ss) {
        if (ss < total) {
            int c = ss % NC;
            uint32_t q = (uint32_t)ss & 3;
            uint32_t gb = 4u * (q & 1);
            if (MODE == 1) {
                int i = ss / NC;
                int t = bid + i * GRID;
                size_t mB = (size_t)t * 128;
                const char* srcA = (const char*)(Ap + ((size_t)c * M_ROWS + mB + crow) * 32 + chalf * 16);
                uint32_t dstA = sb + A_OFF + (q >> 1) * 16384 + crow * 128;
#pragma unroll
                for (int j = 0; j < 2; j++)
                    CP16(dstA + ((gb + 2 * chalf + j) ^ cxor) * 16, srcA + j * 16);
            } else if (c >= RES_CH) {
                // stream B chunk (256 rows x 64B); thread = one row, 4 CP16
                const int row = tid;
                const uint32_t rx = (uint32_t)(row & 7);
                const char* srcB = (const char*)(Wp + ((size_t)c * 256 + row) * 32);
                uint32_t dstB = sb + BS_OFF + (q >> 1) * 32768 + (uint32_t)row * 128;
#pragma unroll
                for (int j = 0; j < 4; j++)
                    CP16(dstB + ((gb + (uint32_t)j) ^ rx) * 16, srcB + j * 16);
            }
        }
        CPCOMMIT();
    };
    auto compute = [&](int sidx) {
        int c = sidx % NC;
        uint32_t q = (uint32_t)sidx & 3;
        uint32_t ga = 4u * (q & 1);
        uint32_t Ab = sb + A_OFF + (q >> 1) * 16384 + aRowOff;
        uint32_t Bb, gb;
        if (MODE == 0 && c >= RES_CH) {
            Bb = sb + BS_OFF + (q >> 1) * 32768 + bRowOff;
            gb = ga;
        } else {
            Bb = sb + (uint32_t)(c >> 1) * 32768 + bRowOff;
            gb = 4u * (uint32_t)(c & 1);
        }
#pragma unroll
        for (int ks = 0; ks < 2; ks++) {
            uint32_t bh[16];
#pragma unroll
            for (int nb = 0; nb < 4; nb++)
                ldsm4(Bb + (uint32_t)nb * 2048 + ((gb + 2 * ks + bKsel) ^ xr) * 16, bh + 4 * nb);
#pragma unroll
            for (int mi = 0; mi < 4; mi++) {
                uint32_t ah[4];
                ldsm4(Ab + mi * 2048 + ((ga + 2 * ks + aKsel) ^ xr) * 16, ah);
#pragma unroll
                for (int nj = 0; nj < 8; nj++)
                    mma_f16(acc[mi][nj], ah, bh[2 * nj], bh[2 * nj + 1]);
            }
        }
    };

    const int rloc = warp_m * 64 + (lane >> 2);
    const int nl0 = warp_n * 64 + (lane & 3) * 2;

    // ---- prologue ----
    prefetch(0);
    prefetch(1);
    if (MODE == 0) {
        loadA_regs(0); storeA_regs(0);
        if (total > 1) { loadA_regs(1); storeA_regs(1); }
        if (total > 2) loadA_regs(2);
    }

    // ---- main loop: ONE barrier per iteration ----
    for (int s = 0; s < total; s++) {
        prefetch(s + 2);
        CPWAIT2();
        __syncthreads();
        compute(s);

        if ((s % NC) == NC - 1) {
            const int t = bid + (s / NC) * GRID;
            const size_t mBase = (size_t)t * 128;
            if (MODE == 0) {
#pragma unroll
                for (int mi = 0; mi < 4; mi++)
#pragma unroll
                    for (int nj = 0; nj < 8; nj++) {
                        int nl = nl0 + nj * 8;
                        float b0v = biasS[nl], b1v = biasS[nl + 1];
                        float v00 = fmaxf(acc[mi][nj][0] + b0v, 0.f);
                        float v01 = fmaxf(acc[mi][nj][1] + b1v, 0.f);
                        float v10 = fmaxf(acc[mi][nj][2] + b0v, 0.f);
                        float v11 = fmaxf(acc[mi][nj][3] + b1v, 0.f);
                        int cpk = nl >> 5, slot = nl & 31;
                        size_t r0 = mBase + rloc + mi * 16;
                        size_t o0 = ((size_t)cpk * M_ROWS + r0) * 32 + slot;
                        size_t o1 = o0 + 8 * 32;
                        *(uint32_t*)(outp + o0) = packf2(v00, v01);
                        *(uint32_t*)(outp + o1) = packf2(v10, v11);
                        acc[mi][nj][0] = 0.f; acc[mi][nj][1] = 0.f;
                        acc[mi][nj][2] = 0.f; acc[mi][nj][3] = 0.f;
                    }
            } else {
                float up[16];
#pragma unroll
                for (int i = 0; i < 16; i++) up[i] = 0.f;
#pragma unroll
                for (int mi = 0; mi < 4; mi++)
#pragma unroll
                    for (int nj = 0; nj < 8; nj++) {
                        int nl = nl0 + nj * 8;
                        float b0v = biasS[nl], b1v = biasS[nl + 1];
                        float w00 = W2s[2 * nl],     w01 = W2s[2 * nl + 1];
                        float w10 = W2s[2 * nl + 2], w11 = W2s[2 * nl + 3];
                        float v00 = fmaxf(acc[mi][nj][0] + b0v, 0.f);
                        float v01 = fmaxf(acc[mi][nj][1] + b1v, 0.f);
                        float v10 = fmaxf(acc[mi][nj][2] + b0v, 0.f);
                        float v11 = fmaxf(acc[mi][nj][3] + b1v, 0.f);
                        up[mi * 4 + 0] += v00 * w00 + v01 * w10;
                        up[mi * 4 + 1] += v00 * w01 + v01 * w11;
                        up[mi * 4 + 2] += v10 * w00 + v11 * w10;
                        up[mi * 4 + 3] += v10 * w01 + v11 * w11;
                        acc[mi][nj][0] = 0.f; acc[mi][nj][1] = 0.f;
                        acc[mi][nj][2] = 0.f; acc[mi][nj][3] = 0.f;
                    }
#pragma unroll
                for (int k = 1; k <= 2; k <<= 1)
#pragma unroll
                    for (int i = 0; i < 16; i++)
                        up[i] += __shfl_xor_sync(0xffffffffu, up[i], k);
                if ((lane & 3) == 0) {
#pragma unroll
                    for (int mi = 0; mi < 4; mi++) {
                        size_t r0 = mBase + rloc + mi * 16;
                        size_t r1 = r0 + 8;
                        atomicAdd(&un[r0 * 2 + 0], up[mi * 4 + 0]);
                        atomicAdd(&un[r0 * 2 + 1], up[mi * 4 + 1]);
                        atomicAdd(&un[r1 * 2 + 0], up[mi * 4 + 2]);
                        atomicAdd(&un[r1 * 2 + 1], up[mi * 4 + 3]);
                    }
                }
            }
        }

        if (MODE == 0) {
            if (s + 2 < total) {
                storeA_regs((uint32_t)(s + 2) & 3);
                if (s + 3 < total) loadA_regs(s + 3);
            }
        }
    }
}

// -------- binary MLP + pairwise config sums ----------------------------------
__global__ __launch_bounds__(128) void binary_kernel(
    const float* __restrict__ ctx, const float* __restrict__ R0,
    const float* __restrict__ r0, const float* __restrict__ R1,
    const float* __restrict__ r1, float* __restrict__ pairsum)
{
    __shared__ float cd[NPAIR][5];
    __shared__ float R0s[5][RHv];
    __shared__ float r0s[RHv];
    __shared__ float R1s[RHv][3];
    __shared__ float r1s[3];
    __shared__ float h2s[NPAIR][RHv];
    __shared__ float bp4s[NPAIR][4];

    int b = blockIdx.x, t = threadIdx.x;
    for (int i = t; i < NPAIR * 5; i += 128) cd[i / 5][i % 5] = ctx[b * NPAIR * 5 + i];
    for (int i = t; i < 5 * RHv; i += 128) R0s[i / RHv][i % RHv] = R0[i];
    if (t < RHv) r0s[t] = r0[t];
    for (int i = t; i < RHv * 3; i += 128) R1s[i / 3][i % 3] = R1[i];
    if (t < 3) r1s[t] = r1[t];
    __syncthreads();

    for (int idx = t; idx < NPAIR * RHv; idx += 128) {
        int p = idx / RHv, u = idx % RHv;
        float v = r0s[u];
#pragma unroll
        for (int x = 0; x < 5; x++) v += cd[p][x] * R0s[x][u];
        h2s[p][u] = fmaxf(v, 0.f);
    }
    __syncthreads();

    if (t < NPAIR * 3) {
        int p = t / 3, y = t % 3;
        float v = r1s[y];
#pragma unroll
        for (int u = 0; u < RHv; u++) v += h2s[p][u] * R1s[u][y];
        if (y == 0) bp4s[p][0] = v;
        else if (y == 1) { bp4s[p][1] = v; bp4s[p][2] = v; }
        else bp4s[p][3] = v;
    }
    __syncthreads();

    int s = t;
    float accv = 0.f;
    int p = 0;
#pragma unroll
    for (int i = 0; i < NE; i++)
#pragma unroll
        for (int j = i + 1; j < NE; j++) {
            int bi = (s >> (6 - i)) & 1;
            int bj = (s >> (6 - j)) & 1;
            accv += bp4s[p][bi * 2 + bj];
            p++;
        }
    pairsum[(size_t)b * NCFG + s] = accv;
}

// ---------------- joint + lse + marginals: one warp per (n,b) -----------------
__global__ __launch_bounds__(256) void joint_kernel(
    const float* __restrict__ un, const float* __restrict__ ps,
    const float* __restrict__ b2v, float* __restrict__ out_marg,
    float* __restrict__ out_joint)
{
    int w = blockIdx.x * 8 + (threadIdx.x >> 5);
    int lane = threadIdx.x & 31;
    int b = w & (BSZv - 1), n = w >> 9;
    size_t nb = (size_t)n * BSZv + b;

    float val = 0.f;
    if (lane < 14) val = un[nb * 14 + lane] + b2v[lane & 1];
    float u[14];
#pragma unroll
    for (int i = 0; i < 14; i++) u[i] = __shfl_sync(0xffffffffu, val, i);

    float j[4], e[4];
    float mx = -1e30f;
#pragma unroll
    for (int q = 0; q < 4; q++) {
        int s = q * 32 + lane;
        float t = ps[(size_t)b * NCFG + s];
#pragma unroll
        for (int i = 0; i < NE; i++) t += u[i * 2 + ((s >> (6 - i)) & 1)];
        j[q] = t;
        mx = fmaxf(mx, t);
    }
#pragma unroll
    for (int o = 16; o; o >>= 1) mx = fmaxf(mx, __shfl_xor_sync(0xffffffffu, mx, o));

    float p1[NE], p0[NE];
#pragma unroll
    for (int i = 0; i < NE; i++) { p1[i] = 0.f; p0[i] = 0.f; }
#pragma unroll
    for (int q = 0; q < 4; q++) {
        int s = q * 32 + lane;
        e[q] = __expf(j[q] - mx);
#pragma unroll
        for (int i = 0; i < NE; i++) {
            if ((s >> (6 - i)) & 1) p1[i] += e[q];
            else p0[i] += e[q];
        }
    }
#pragma unroll
    for (int o = 16; o; o >>= 1)
#pragma unroll
        for (int i = 0; i < NE; i++) {
            p1[i] += __shfl_xor_sync(0xffffffffu, p1[i], o);
            p0[i] += __shfl_xor_sync(0xffffffffu, p0[i], o);
        }

    float lt = __logf(p1[0] + p0[0]);
#pragma unroll
    for (int q = 0; q < 4; q++)
        out_joint[nb * NCFG + q * 32 + lane] = j[q] - mx - lt;
    if (lane < NE)
        out_marg[nb * NE + lane] = __logf(p1[lane]) - __logf(p0[lane]);
}

// ---------------- launch -------------------------------------------------------
extern "C" void kernel_launch(void* const* d_in, const int* in_sizes, int n_in,
                              void* d_out, int out_size)
{
    const float* input = (const float*)d_in[0];
    const float* ctx   = (const float*)d_in[1];
    const float* W0 = (const float*)d_in[4];
    const float* b0 = (const float*)d_in[5];
    const float* W1 = (const float*)d_in[6];
    const float* b1 = (const float*)d_in[7];
    const float* W2 = (const float*)d_in[8];
    const float* b2 = (const float*)d_in[9];
    const float* R0 = (const float*)d_in[10];
    const float* r0 = (const float*)d_in[11];
    const float* R1 = (const float*)d_in[12];
    const float* r1 = (const float*)d_in[13];

    float* out = (float*)d_out;
    float* out_marg = out;
    float* out_joint = out + (size_t)M_ROWS;

    __half *w0p, *w1p, *h1p;
    float *un, *psum;
    cudaGetSymbolAddress((void**)&w0p, g_w0p);
    cudaGetSymbolAddress((void**)&w1p, g_w1p);
    cudaGetSymbolAddress((void**)&h1p, g_h1p);
    cudaGetSymbolAddress((void**)&un, g_un);
    cudaGetSymbolAddress((void**)&psum, g_pairsum);

    cudaFuncSetAttribute(gemm_tc<DIN, 0>, cudaFuncAttributeMaxDynamicSharedMemorySize, SMEM_SZ0);
    cudaFuncSetAttribute(gemm_tc<DHv, 1>, cudaFuncAttributeMaxDynamicSharedMemorySize, SMEM_SZ1);

    pack_weights<<<DIN, 256>>>(W0, w0p, DIN);
    pack_weights<<<DHv, 256>>>(W1, w1p, DHv);
    cudaMemsetAsync(un, 0, (size_t)M_ROWS * 2 * sizeof(float));

    gemm_tc<DIN, 0><<<PGRID, 256, SMEM_SZ0>>>(
        input, nullptr, w0p, b0, nullptr, h1p, nullptr);
    gemm_tc<DHv, 1><<<PGRID, 256, SMEM_SZ1>>>(
        nullptr, h1p, w1p, b1, W2, nullptr, un);
    binary_kernel<<<BSZv, 128>>>(ctx, R0, r0, R1, r1, psum);
    joint_kernel<<<(NN * BSZv) / 8, 256>>>(un, psum, b2, out_marg, out_joint);
}